// round 3
// baseline (speedup 1.0000x reference)
#include <cuda_runtime.h>
#include <cuda_bf16.h>

// Problem constants (fixed by the reference's setup_inputs)
#define BQ 4096
#define NQ 128
#define FQ 64
#define HIST 1024      // ids in [0,1000); -1 padding handled via unsigned compare
#define TROWS 129      // counts range 0..128 inclusive
#define BPB 4          // batches per block in the count kernel

// MLP lookup table: T[c][g] = b2[g] + sum_f relu(c*w1[f]+b1[f]) * w2[g*F+f]
__device__ float g_table[TROWS * FQ];
// Packed per-element counts: (c_ss, c_sd, c_dd, c_ds)
__device__ uchar4 g_cnts[BQ * NQ];

// ---------------------------------------------------------------------------
// Kernel 1: per-batch packed histograms -> g_cnts. First 129 blocks also
// compute one MLP-table row each (overlapped with the histogram atomics).
// Shared: hist 8KB + h 256B.
// ---------------------------------------------------------------------------
__global__ __launch_bounds__(256)
void count_kernel(const int* __restrict__ src,
                  const int* __restrict__ dst,
                  const float* __restrict__ w1,
                  const float* __restrict__ b1,
                  const float* __restrict__ w2,
                  const float* __restrict__ b2) {
    __shared__ unsigned int hist[2][HIST];  // packs: b0.src[0:8) b0.dst[8:16) b1.src[16:24) b1.dst[24:32)
    __shared__ float h[FQ];

    const int tid = threadIdx.x;

    for (int idx = tid; idx < 2 * HIST; idx += 256) {
        (&hist[0][0])[idx] = 0u;
    }
    // Table hidden layer for this block's row (if any)
    const bool tb = (blockIdx.x < TROWS);
    if (tb && tid < FQ) {
        h[tid] = fmaxf((float)blockIdx.x * w1[tid] + b1[tid], 0.0f);  // w1 shape (F,1)
    }
    __syncthreads();

    // Table output row: overlaps with other warps' histogram work.
    if (tb && tid < FQ) {
        float acc = b2[tid];
#pragma unroll
        for (int f = 0; f < FQ; f++) {
            acc += h[f] * w2[tid * FQ + f];  // einsum 'bncf,gf->bncg' => w2[g, f]
        }
        g_table[blockIdx.x * FQ + tid] = acc;
    }

    // Histogram: 4 batches x 128 ids = 512 items, 2 per thread.
    int s_ids[2], d_ids[2];
#pragma unroll
    for (int it = 0; it < 2; it++) {
        const int idx = it * 256 + tid;
        const int lb = idx >> 7;             // local batch 0..3
        const int i  = idx & 127;
        const long long b = (long long)blockIdx.x * BPB + lb;
        const int s = src[b * NQ + i];
        const int d = dst[b * NQ + i];
        s_ids[it] = s; d_ids[it] = d;
        const int p  = lb >> 1;
        const int sh = (lb & 1) * 16;
        if ((unsigned)s < HIST) atomicAdd(&hist[p][s], 1u << sh);
        if ((unsigned)d < HIST) atomicAdd(&hist[p][d], 1u << (sh + 8));
    }
    __syncthreads();

    // Extract counts. Padded id (-1) -> zero counts (reference's where(pad,0,freq);
    // MLP(0) is still applied via table row 0).
#pragma unroll
    for (int it = 0; it < 2; it++) {
        const int idx = it * 256 + tid;
        const int lb = idx >> 7;
        const int i  = idx & 127;
        const int p  = lb >> 1;
        const int sh = (lb & 1) * 16;
        const int s = s_ids[it], d = d_ids[it];
        const unsigned hs = ((unsigned)s < HIST) ? hist[p][s] : 0u;
        const unsigned hd = ((unsigned)d < HIST) ? hist[p][d] : 0u;
        uchar4 c;
        c.x = (unsigned char)((hs >> sh)       & 0xFFu);  // c_ss
        c.y = (unsigned char)((hs >> (sh + 8)) & 0xFFu);  // c_sd
        c.z = (unsigned char)((hd >> (sh + 8)) & 0xFFu);  // c_dd
        c.w = (unsigned char)((hd >> sh)       & 0xFFu);  // c_ds
        g_cnts[((long long)blockIdx.x * BPB + lb) * NQ + i] = c;
    }
}

// ---------------------------------------------------------------------------
// Row fetch for the write kernel: counts 0..3 (>99.9% of cases) come from
// registers; rare larger counts fall back to an L1/L2-resident global load.
// ---------------------------------------------------------------------------
__device__ __forceinline__ float4 frow(int c, const float4 r0, const float4 r1,
                                       const float4 r2, const float4 r3, int g4) {
    if (c < 4) {
        float4 v = r0;
        if (c == 1) v = r1;
        else if (c == 2) v = r2;
        else if (c == 3) v = r3;
        return v;
    }
    return *(const float4*)(g_table + c * FQ + g4);
}

// ---------------------------------------------------------------------------
// Kernel 2: pure streaming write. No smem, no barriers. One block per batch.
// Each thread owns a fixed g4 slice (256 % 16 == 0), so rows 0..3 live in
// registers for the whole kernel. Fully coalesced __stcs float4 stores.
// ---------------------------------------------------------------------------
__global__ __launch_bounds__(256)
void write_kernel(float* __restrict__ out) {
    const int tid = threadIdx.x;
    const int b   = blockIdx.x;
    const int g4  = (tid & 15) * 4;

    const float4 r0 = *(const float4*)(g_table + 0 * FQ + g4);
    const float4 r1 = *(const float4*)(g_table + 1 * FQ + g4);
    const float4 r2 = *(const float4*)(g_table + 2 * FQ + g4);
    const float4 r3 = *(const float4*)(g_table + 3 * FQ + g4);

    const uchar4* __restrict__ cb = g_cnts + (size_t)b * NQ;
    float4* const osrc = (float4*)out + (size_t)b * (NQ * FQ / 4);
    float4* const odst = osrc + (size_t)BQ * (NQ * FQ / 4);

#pragma unroll
    for (int k = 0; k < 8; k++) {
        const int lin = k * 256 + tid;
        const int i   = lin >> 4;
        const uchar4 c = cb[i];   // 16 lanes broadcast the same word

        // src_feat = T[c_ss] + T[c_sd]
        float4 a  = frow(c.x, r0, r1, r2, r3, g4);
        float4 a2 = frow(c.y, r0, r1, r2, r3, g4);
        a.x += a2.x; a.y += a2.y; a.z += a2.z; a.w += a2.w;
        __stcs(&osrc[lin], a);

        // dst_feat = T[c_dd] + T[c_ds]
        float4 e  = frow(c.z, r0, r1, r2, r3, g4);
        float4 e2 = frow(c.w, r0, r1, r2, r3, g4);
        e.x += e2.x; e.y += e2.y; e.z += e2.z; e.w += e2.w;
        __stcs(&odst[lin], e);
    }
}

// ---------------------------------------------------------------------------
// Launch. Inputs (metadata order): src_ids[B*N] i32, dst_ids[B*N] i32,
// w1[F] f32, b1[F] f32, w2[F*F] f32, b2[F] f32. Output: f32, 2*B*N*F
// (src_feat flattened, then dst_feat flattened).
// ---------------------------------------------------------------------------
extern "C" void kernel_launch(void* const* d_in, const int* in_sizes, int n_in,
                              void* d_out, int out_size) {
    const int*   src = (const int*)d_in[0];
    const int*   dst = (const int*)d_in[1];
    const float* w1  = (const float*)d_in[2];
    const float* b1  = (const float*)d_in[3];
    const float* w2  = (const float*)d_in[4];
    const float* b2  = (const float*)d_in[5];
    float* out = (float*)d_out;

    count_kernel<<<BQ / BPB, 256>>>(src, dst, w1, b1, w2, b2);
    write_kernel<<<BQ, 256>>>(out);
}

// round 4
// speedup vs baseline: 1.0006x; 1.0006x over previous
#include <cuda_runtime.h>
#include <cuda_bf16.h>

// Problem constants (fixed by the reference's setup_inputs)
#define BQ 4096
#define NQ 128
#define FQ 64
#define HIST 1024      // ids in [0,1000); -1 padding handled via unsigned compare
#define TROWS 129      // counts range 0..128 inclusive
#define BPB 4          // batches per block in the count kernel
#define PSTRIDE 68     // padded pair-sum row stride (floats)

// MLP lookup table: T[c][g] = b2[g] + sum_f relu(c*w1[f]+b1[f]) * w2[g*F+f]
__device__ float g_table[TROWS * FQ];
// Packed per-element counts: (c_ss, c_sd, c_dd, c_ds)
__device__ uchar4 g_cnts[BQ * NQ];

// ---------------------------------------------------------------------------
// Kernel 1: per-batch packed histograms -> g_cnts. First 129 blocks also
// compute one MLP-table row each (overlapped with the histogram atomics).
// ---------------------------------------------------------------------------
__global__ __launch_bounds__(256)
void count_kernel(const int* __restrict__ src,
                  const int* __restrict__ dst,
                  const float* __restrict__ w1,
                  const float* __restrict__ b1,
                  const float* __restrict__ w2,
                  const float* __restrict__ b2) {
    __shared__ unsigned int hist[2][HIST];  // packs: b0.src[0:8) b0.dst[8:16) b1.src[16:24) b1.dst[24:32)
    __shared__ float h[FQ];

    const int tid = threadIdx.x;

    for (int idx = tid; idx < 2 * HIST; idx += 256) {
        (&hist[0][0])[idx] = 0u;
    }
    const bool tb = (blockIdx.x < TROWS);
    if (tb && tid < FQ) {
        h[tid] = fmaxf((float)blockIdx.x * w1[tid] + b1[tid], 0.0f);  // w1 shape (F,1)
    }
    __syncthreads();

    // Table output row: overlaps with other warps' histogram work.
    if (tb && tid < FQ) {
        float acc = b2[tid];
#pragma unroll
        for (int f = 0; f < FQ; f++) {
            acc += h[f] * w2[tid * FQ + f];  // einsum 'bncf,gf->bncg' => w2[g, f]
        }
        g_table[blockIdx.x * FQ + tid] = acc;
    }

    // Histogram: 4 batches x 128 ids = 512 items, 2 per thread.
    int s_ids[2], d_ids[2];
#pragma unroll
    for (int it = 0; it < 2; it++) {
        const int idx = it * 256 + tid;
        const int lb = idx >> 7;             // local batch 0..3
        const int i  = idx & 127;
        const long long b = (long long)blockIdx.x * BPB + lb;
        const int s = src[b * NQ + i];
        const int d = dst[b * NQ + i];
        s_ids[it] = s; d_ids[it] = d;
        const int p  = lb >> 1;
        const int sh = (lb & 1) * 16;
        if ((unsigned)s < HIST) atomicAdd(&hist[p][s], 1u << sh);
        if ((unsigned)d < HIST) atomicAdd(&hist[p][d], 1u << (sh + 8));
    }
    __syncthreads();

    // Extract counts. Padded id (-1) -> zero counts (reference's where(pad,0,freq);
    // MLP(0) is still applied via table row 0).
#pragma unroll
    for (int it = 0; it < 2; it++) {
        const int idx = it * 256 + tid;
        const int lb = idx >> 7;
        const int i  = idx & 127;
        const int p  = lb >> 1;
        const int sh = (lb & 1) * 16;
        const int s = s_ids[it], d = d_ids[it];
        const unsigned hs = ((unsigned)s < HIST) ? hist[p][s] : 0u;
        const unsigned hd = ((unsigned)d < HIST) ? hist[p][d] : 0u;
        uchar4 c;
        c.x = (unsigned char)((hs >> sh)       & 0xFFu);  // c_ss
        c.y = (unsigned char)((hs >> (sh + 8)) & 0xFFu);  // c_sd
        c.z = (unsigned char)((hd >> (sh + 8)) & 0xFFu);  // c_dd
        c.w = (unsigned char)((hd >> sh)       & 0xFFu);  // c_ds
        g_cnts[((long long)blockIdx.x * BPB + lb) * NQ + i] = c;
    }
}

// ---------------------------------------------------------------------------
// Kernel 2: streaming write. One block per batch. Precompute 16 pair-sum rows
// S[a*4+b] = T[a] + T[b] in shared once; hot loop = LDS.128 + STG.128 only.
// Counts >= 4 (P ~ 3e-4) fall back to two L2-resident global loads.
// Shared: 16*68*4 + 512 = 4.9 KB.
// ---------------------------------------------------------------------------
__global__ __launch_bounds__(256)
void write_kernel(float* __restrict__ out) {
    __shared__ float S[16 * PSTRIDE];
    __shared__ uchar4 sc[NQ];

    const int tid = threadIdx.x;
    const int b   = blockIdx.x;

    // Stage this batch's counts (512 B).
    if (tid < NQ) sc[tid] = g_cnts[(size_t)b * NQ + tid];

    // Build pair-sum table: 16 rows x 16 float4 = 256 entries, 1 per thread.
    {
        const int r  = tid >> 4;          // pair index 0..15 -> (a = r>>2, b = r&3)
        const int q  = tid & 15;          // float4 column
        const float4 ta = *(const float4*)(g_table + (r >> 2) * FQ + q * 4);
        const float4 tb = *(const float4*)(g_table + (r & 3) * FQ + q * 4);
        float4 v;
        v.x = ta.x + tb.x; v.y = ta.y + tb.y; v.z = ta.z + tb.z; v.w = ta.w + tb.w;
        *(float4*)&S[r * PSTRIDE + q * 4] = v;
    }
    __syncthreads();

    const int g4 = (tid & 15) * 4;
    float4* const osrc = (float4*)out + (size_t)b * (NQ * FQ / 4);
    float4* const odst = osrc + (size_t)BQ * (NQ * FQ / 4);

#pragma unroll
    for (int k = 0; k < 8; k++) {
        const int lin = k * 256 + tid;
        const int i   = lin >> 4;
        const uchar4 c = sc[i];   // 16 lanes broadcast the same word

        // src_feat = T[c_ss] + T[c_sd]
        float4 a;
        if (((int)c.x | (int)c.y) < 4) {
            a = *(const float4*)&S[((int)c.x * 4 + (int)c.y) * PSTRIDE + g4];
        } else {
            const float4 u = *(const float4*)(g_table + (int)c.x * FQ + g4);
            const float4 v = *(const float4*)(g_table + (int)c.y * FQ + g4);
            a.x = u.x + v.x; a.y = u.y + v.y; a.z = u.z + v.z; a.w = u.w + v.w;
        }
        __stcs(&osrc[lin], a);

        // dst_feat = T[c_dd] + T[c_ds]
        float4 e;
        if (((int)c.z | (int)c.w) < 4) {
            e = *(const float4*)&S[((int)c.z * 4 + (int)c.w) * PSTRIDE + g4];
        } else {
            const float4 u = *(const float4*)(g_table + (int)c.z * FQ + g4);
            const float4 v = *(const float4*)(g_table + (int)c.w * FQ + g4);
            e.x = u.x + v.x; e.y = u.y + v.y; e.z = u.z + v.z; e.w = u.w + v.w;
        }
        __stcs(&odst[lin], e);
    }
}

// ---------------------------------------------------------------------------
// Launch. Inputs (metadata order): src_ids[B*N] i32, dst_ids[B*N] i32,
// w1[F] f32, b1[F] f32, w2[F*F] f32, b2[F] f32. Output: f32, 2*B*N*F
// (src_feat flattened, then dst_feat flattened).
// ---------------------------------------------------------------------------
extern "C" void kernel_launch(void* const* d_in, const int* in_sizes, int n_in,
                              void* d_out, int out_size) {
    const int*   src = (const int*)d_in[0];
    const int*   dst = (const int*)d_in[1];
    const float* w1  = (const float*)d_in[2];
    const float* b1  = (const float*)d_in[3];
    const float* w2  = (const float*)d_in[4];
    const float* b2  = (const float*)d_in[5];
    float* out = (float*)d_out;

    count_kernel<<<BQ / BPB, 256>>>(src, dst, w1, b1, w2, b2);
    write_kernel<<<BQ, 256>>>(out);
}